// round 17
// baseline (speedup 1.0000x reference)
#include <cuda_runtime.h>
#include <cuda_fp16.h>

// WarpDTI fused — R16 base + z-pair duplication in the packed DTI texture.
// Packed layout (per batch): 3 planes of uint2, one per channel pair (0,1),
// (2,3), (4,5); element at voxel v = { half2(ca[z],cb[z]), half2(ca[z+1],cb[z+1]) }
// with z+1 clamped to 63. The trilinear gather then needs only the 4 xy-corners
// at z0: 12x LDG.64 (8B/lane, near-consecutive z addresses -> ~same L1 line set
// as the former 24x LDG.32). J/R/lerp all fp32; only M storage is fp16.

constexpr int HWD  = 64 * 64 * 64;   // 262144 = 2^18
constexpr int MAXB = 2;

__device__ uint2 g_pk[(size_t)MAXB * 3 * HWD];   // 12.6 MB scratch

__global__ __launch_bounds__(256)
void pack_half_kernel(const float* __restrict__ dti, int total4)
{
    int idx = blockIdx.x * blockDim.x + threadIdx.x;   // one thread = 4 voxels
    if (idx >= total4) return;
    int vox = (idx << 2) & (HWD - 1);
    int b   = idx >> 16;
    int zb  = vox & 63;                   // in {0,4,...,60}
    bool last = (zb == 60);               // row end: z+1 of voxel 3 clamps to 63

    const float* p = dti + (size_t)b * 6 * HWD + vox;
    float4 c[6];
    float  nx[6];
    #pragma unroll
    for (int ch = 0; ch < 6; ch++) {
        c[ch]  = __ldg((const float4*)(p + ch * HWD));
        nx[ch] = last ? c[ch].w : __ldg(p + ch * HWD + 4);
    }

    uint2* g = g_pk + (size_t)b * 3 * HWD;
    #pragma unroll
    for (int pl = 0; pl < 3; pl++) {
        float4 A = c[2 * pl], B = c[2 * pl + 1];
        float An = nx[2 * pl], Bn = nx[2 * pl + 1];
        __half2 hx = __floats2half2_rn(A.x, B.x);
        __half2 hy = __floats2half2_rn(A.y, B.y);
        __half2 hz = __floats2half2_rn(A.z, B.z);
        __half2 hw = __floats2half2_rn(A.w, B.w);
        __half2 hn = __floats2half2_rn(An, Bn);
        uint4 o0 = make_uint4(*(unsigned*)&hx, *(unsigned*)&hy,
                              *(unsigned*)&hy, *(unsigned*)&hz);
        uint4 o1 = make_uint4(*(unsigned*)&hz, *(unsigned*)&hw,
                              *(unsigned*)&hw, *(unsigned*)&hn);
        *(uint4*)(g + (size_t)pl * HWD + vox)     = o0;
        *(uint4*)(g + (size_t)pl * HWD + vox + 2) = o1;
    }
}

__global__ __launch_bounds__(256)
void warp_dti_kernel(const float* __restrict__ ddf,
                     float* __restrict__ out,
                     int total)
{
    int idx = blockIdx.x * blockDim.x + threadIdx.x;
    if (idx >= total) return;

    int vox = idx & (HWD - 1);
    int b   = idx >> 18;
    int z   =  vox        & 63;
    int y   = (vox >> 6)  & 63;
    int x   =  vox >> 12;

    const float* u = ddf + (size_t)b * 3 * HWD;

    float u0 = __ldg(u +           vox);
    float u1 = __ldg(u +     HWD + vox);
    float u2 = __ldg(u + 2 * HWD + vox);

    // ---------- Jacobian J = I + du_i/dx_j (jnp.gradient semantics) --------
    float J00, J01, J02, J10, J11, J12, J20, J21, J22;
    {   // axis 0 (x), stride 4096
        int ip = (x < 63) ? x + 1 : 63;
        int im = (x > 0 ) ? x - 1 : 0;
        float s = (ip - im == 2) ? 0.5f : 1.0f;
        int op = (ip - x) << 12, om = (im - x) << 12;
        J00 = (__ldg(u +           vox + op) - __ldg(u +           vox + om)) * s;
        J10 = (__ldg(u + HWD     + vox + op) - __ldg(u + HWD     + vox + om)) * s;
        J20 = (__ldg(u + 2 * HWD + vox + op) - __ldg(u + 2 * HWD + vox + om)) * s;
    }
    {   // axis 1 (y), stride 64
        int ip = (y < 63) ? y + 1 : 63;
        int im = (y > 0 ) ? y - 1 : 0;
        float s = (ip - im == 2) ? 0.5f : 1.0f;
        int op = (ip - y) << 6, om = (im - y) << 6;
        J01 = (__ldg(u +           vox + op) - __ldg(u +           vox + om)) * s;
        J11 = (__ldg(u + HWD     + vox + op) - __ldg(u + HWD     + vox + om)) * s;
        J21 = (__ldg(u + 2 * HWD + vox + op) - __ldg(u + 2 * HWD + vox + om)) * s;
    }
    {   // axis 2 (z), stride 1
        int ip = (z < 63) ? z + 1 : 63;
        int im = (z > 0 ) ? z - 1 : 0;
        float s = (ip - im == 2) ? 0.5f : 1.0f;
        int op = ip - z, om = im - z;
        J02 = (__ldg(u +           vox + op) - __ldg(u +           vox + om)) * s;
        J12 = (__ldg(u + HWD     + vox + op) - __ldg(u + HWD     + vox + om)) * s;
        J22 = (__ldg(u + 2 * HWD + vox + op) - __ldg(u + 2 * HWD + vox + om)) * s;
    }
    J00 += 1.0f; J11 += 1.0f; J22 += 1.0f;

    // ---------- trilinear warp (border clamp, align_corners) ----------
    float cx = fminf(fmaxf(u0 + (float)x, 0.0f), 63.0f);
    float cy = fminf(fmaxf(u1 + (float)y, 0.0f), 63.0f);
    float cz = fminf(fmaxf(u2 + (float)z, 0.0f), 63.0f);
    float xf = floorf(cx), yf = floorf(cy), zf = floorf(cz);
    float fx = cx - xf,   fy = cy - yf,   fz = cz - zf;
    int x0 = (int)xf, y0 = (int)yf, z0 = (int)zf;
    int x1 = min(x0 + 1, 63), y1 = min(y0 + 1, 63);

    // 4 xy-corner indices at z0 (z1 tap is baked into the packed element)
    int cid0 = (((x0 << 6) + y0) << 6) + z0;
    int cid1 = (((x0 << 6) + y1) << 6) + z0;
    int cid2 = (((x1 << 6) + y0) << 6) + z0;
    int cid3 = (((x1 << 6) + y1) << 6) + z0;

    float wx0 = 1.0f - fx, wy0 = 1.0f - fy, wz0 = 1.0f - fz;
    // per-corner (lo,hi) weights
    float wl0 = wx0 * wy0 * wz0, wh0 = wx0 * wy0 * fz;
    float wl1 = wx0 * fy  * wz0, wh1 = wx0 * fy  * fz;
    float wl2 = fx  * wy0 * wz0, wh2 = fx  * wy0 * fz;
    float wl3 = fx  * fy  * wz0, wh3 = fx  * fy  * fz;

    // ---------- gather: 3 pair-planes x 4 corners = 12 LDG.64 ----------
    float m[6];
    const uint2* img = g_pk + (size_t)b * 3 * HWD;
    #pragma unroll
    for (int pl = 0; pl < 3; pl++) {
        const uint2* p = img + (size_t)pl * HWD;
        uint2 v0 = __ldg(p + cid0);
        uint2 v1 = __ldg(p + cid1);
        uint2 v2 = __ldg(p + cid2);
        uint2 v3 = __ldg(p + cid3);
        float2 l0 = __half22float2(*(__half2*)&v0.x), h0 = __half22float2(*(__half2*)&v0.y);
        float2 l1 = __half22float2(*(__half2*)&v1.x), h1 = __half22float2(*(__half2*)&v1.y);
        float2 l2 = __half22float2(*(__half2*)&v2.x), h2 = __half22float2(*(__half2*)&v2.y);
        float2 l3 = __half22float2(*(__half2*)&v3.x), h3 = __half22float2(*(__half2*)&v3.y);
        m[2 * pl]     = wl0 * l0.x + wh0 * h0.x + wl1 * l1.x + wh1 * h1.x
                      + wl2 * l2.x + wh2 * h2.x + wl3 * l3.x + wh3 * h3.x;
        m[2 * pl + 1] = wl0 * l0.y + wh0 * h0.y + wl1 * l1.y + wh1 * h1.y
                      + wl2 * l2.y + wh2 * h2.y + wl3 * l3.y + wh3 * h3.y;
    }

    // ---------- polar factor R = U V^T ----------
    float X00 = J00, X01 = J01, X02 = J02;
    float X10 = J10, X11 = J11, X12 = J12;
    float X20 = J20, X21 = J21, X22 = J22;

    // 2 scaled Newton iterations (Frobenius mu, fast-math — self-correcting)
    #pragma unroll
    for (int it = 0; it < 2; ++it) {
        float C00 = X11 * X22 - X12 * X21;
        float C01 = X12 * X20 - X10 * X22;
        float C02 = X10 * X21 - X11 * X20;
        float C10 = X21 * X02 - X22 * X01;
        float C11 = X22 * X00 - X20 * X02;
        float C12 = X20 * X01 - X21 * X00;
        float C20 = X01 * X12 - X02 * X11;
        float C21 = X02 * X10 - X00 * X12;
        float C22 = X00 * X11 - X01 * X10;
        float det = X00 * C00 + X01 * C01 + X02 * C02;
        float adet = fmaxf(fabsf(det), 1e-12f);
        float sdet = (det < 0.0f) ? -adet : adet;
        float nX = X00*X00 + X01*X01 + X02*X02 + X10*X10 + X11*X11 + X12*X12
                 + X20*X20 + X21*X21 + X22*X22;
        float nC = C00*C00 + C01*C01 + C02*C02 + C10*C10 + C11*C11 + C12*C12
                 + C20*C20 + C21*C21 + C22*C22;
        float mu = exp2f(0.25f * __log2f(nC / nX)) * rsqrtf(adet);
        mu = fminf(fmaxf(mu, 1e-4f), 1e4f);
        float a = 0.5f * mu;
        float c = __fdividef(0.5f, mu * sdet);
        X00 = a * X00 + c * C00; X01 = a * X01 + c * C01; X02 = a * X02 + c * C02;
        X10 = a * X10 + c * C10; X11 = a * X11 + c * C11; X12 = a * X12 + c * C12;
        X20 = a * X20 + c * C20; X21 = a * X21 + c * C21; X22 = a * X22 + c * C22;
    }
    // 3 plain Newton iterations: X <- 0.5*(X + cof(X)/det)
    #pragma unroll
    for (int it = 0; it < 3; ++it) {
        float C00 = X11 * X22 - X12 * X21;
        float C01 = X12 * X20 - X10 * X22;
        float C02 = X10 * X21 - X11 * X20;
        float C10 = X21 * X02 - X22 * X01;
        float C11 = X22 * X00 - X20 * X02;
        float C12 = X20 * X01 - X21 * X00;
        float C20 = X01 * X12 - X02 * X11;
        float C21 = X02 * X10 - X00 * X12;
        float C22 = X00 * X11 - X01 * X10;
        float det = X00 * C00 + X01 * C01 + X02 * C02;
        float adet = fmaxf(fabsf(det), 1e-12f);
        float sdet = (det < 0.0f) ? -adet : adet;
        float c = __fdividef(0.5f, sdet);
        X00 = 0.5f * X00 + c * C00; X01 = 0.5f * X01 + c * C01; X02 = 0.5f * X02 + c * C02;
        X10 = 0.5f * X10 + c * C10; X11 = 0.5f * X11 + c * C11; X12 = 0.5f * X12 + c * C12;
        X20 = 0.5f * X20 + c * C20; X21 = 0.5f * X21 + c * C21; X22 = 0.5f * X22 + c * C22;
    }

    // ---------- S = R^T M R, lower triangle ----------
    float w0x = m[0]*X00 + m[1]*X10 + m[3]*X20;
    float w0y = m[1]*X00 + m[2]*X10 + m[4]*X20;
    float w0z = m[3]*X00 + m[4]*X10 + m[5]*X20;
    float w1x = m[0]*X01 + m[1]*X11 + m[3]*X21;
    float w1y = m[1]*X01 + m[2]*X11 + m[4]*X21;
    float w1z = m[3]*X01 + m[4]*X11 + m[5]*X21;
    float w2x = m[0]*X02 + m[1]*X12 + m[3]*X22;
    float w2y = m[1]*X02 + m[2]*X12 + m[4]*X22;
    float w2z = m[3]*X02 + m[4]*X12 + m[5]*X22;

    float S00 = X00*w0x + X10*w0y + X20*w0z;
    float S10 = X01*w0x + X11*w0y + X21*w0z;
    float S11 = X01*w1x + X11*w1y + X21*w1z;
    float S20 = X02*w0x + X12*w0y + X22*w0z;
    float S21 = X02*w1x + X12*w1y + X22*w1z;
    float S22 = X02*w2x + X12*w2y + X22*w2z;

    float* o = out + (size_t)b * 6 * HWD + vox;
    o[0]       = S00;
    o[HWD]     = S10;
    o[2 * HWD] = S11;
    o[3 * HWD] = S20;
    o[4 * HWD] = S21;
    o[5 * HWD] = S22;
}

extern "C" void kernel_launch(void* const* d_in, const int* in_sizes, int n_in,
                              void* d_out, int out_size)
{
    const float* dti = (const float*)d_in[0];
    const float* ddf = (const float*)d_in[1];
    int s0 = in_sizes[0], s1 = in_sizes[1];
    if (s0 < s1) { const float* t = dti; dti = ddf; ddf = t; int ts = s0; s0 = s1; s1 = ts; }
    int B = s1 / (3 * HWD);
    if (B > MAXB) B = MAXB;
    int total  = B * HWD;
    int total4 = total >> 2;
    int threads = 256;
    pack_half_kernel<<<(total4 + threads - 1) / threads, threads>>>(dti, total4);
    warp_dti_kernel<<<(total  + threads - 1) / threads, threads>>>(ddf, (float*)d_out, total);
}